// round 8
// baseline (speedup 1.0000x reference)
#include <cuda_runtime.h>
#include <cuda_fp16.h>
#include <cstdint>

// ---------------------------------------------------------------------------
// Problem constants
// ---------------------------------------------------------------------------
#define BATCH    8192
#define IN_SIZE  512
#define OUT_SIZE 512
#define KDIM     (IN_SIZE * 8)        // 4096

// GEMM tiling
#define BM       128
#define BN       128
#define BK       64                    // 64 fp16 = 128 B rows
#define STAGES   4
#define NTILES_N (OUT_SIZE / BN)       // 4
#define NTILES_M (BATCH / BM)          // 64
#define NKC      (KDIM / BK)           // 64
#define TOTAL_UNITS (NTILES_M * NTILES_N * NKC)   // 16384
#define A_BYTES  (BM * 128)
#define B_BYTES  (BN * 128)
#define STAGE_BYTES (A_BYTES + B_BYTES)
#define SMEM_TOTAL  (STAGES * STAGE_BYTES)   // 131072

#define NTHREADS 320                   // 8 compute warps + 2 producer warps

// ---------------------------------------------------------------------------
// Scratch (device globals -- no cudaMalloc allowed)
// ---------------------------------------------------------------------------
__device__ __half g_B[(size_t)OUT_SIZE * KDIM];   // 4 MB: coeff*weight, fp16

__device__ __forceinline__ uint32_t smem_u32(const void* p) {
    uint32_t a;
    asm("{ .reg .u64 t; cvta.to.shared.u64 t, %1; cvt.u32.u64 %0, t; }"
        : "=r"(a) : "l"(p));
    return a;
}

// Closed-form uniform cubic B-spline: 8 basis values for one x, packed fp16.
__device__ __forceinline__ uint4 basis8(float xv) {
    xv = fminf(1.0f, fmaxf(-1.0f, xv));
    float u = (xv + 1.0f) * 3.5f;          // / h, h = 2/7
    int i = min(7, (int)u);
    float t = u - (float)i;
    const float k6 = 1.0f / 6.0f;
    float t2 = t * t, t3 = t2 * t, omt = 1.0f - t;
    float v0 = t3 * k6;                                  // d = 0  (j == i)
    float v1 = (1.0f + 3.0f * (t + t2 - t3)) * k6;       // d = 1
    float v2 = (4.0f - 6.0f * t2 + 3.0f * t3) * k6;      // d = 2
    float v3 = omt * omt * omt * k6;                     // d = 3  (j == i-3)
    float o[8];
#pragma unroll
    for (int j = 0; j < 8; j++) {
        int d = i - j;
        o[j] = (d == 0) ? v0 : (d == 1) ? v1 : (d == 2) ? v2
             : (d == 3) ? v3 : 0.0f;
    }
    union { uint4 uu; __half2 hh[4]; } v;
    v.hh[0] = __floats2half2_rn(o[0], o[1]);
    v.hh[1] = __floats2half2_rn(o[2], o[3]);
    v.hh[2] = __floats2half2_rn(o[4], o[5]);
    v.hh[3] = __floats2half2_rn(o[6], o[7]);
    return v.uu;
}

// ---------------------------------------------------------------------------
// Kernel 1: B matrix prep  g_B[o, i*8+g] = coeff[o,i,g] * w[o,i]  (fp16)
// ---------------------------------------------------------------------------
__global__ void prep_kernel(const float* __restrict__ w, const float* __restrict__ coef) {
    int idx = blockIdx.x * blockDim.x + threadIdx.x;   // (o, i)
    float wv = w[idx];
    const float4* c4 = reinterpret_cast<const float4*>(coef) + (size_t)idx * 2;
    float4 a = c4[0], b = c4[1];
    union { uint4 u; __half2 h[4]; } v;
    v.h[0] = __floats2half2_rn(a.x * wv, a.y * wv);
    v.h[1] = __floats2half2_rn(a.z * wv, a.w * wv);
    v.h[2] = __floats2half2_rn(b.x * wv, b.y * wv);
    v.h[3] = __floats2half2_rn(b.z * wv, b.w * wv);
    reinterpret_cast<uint4*>(g_B)[idx] = v.u;
}

// ---------------------------------------------------------------------------
// Kernel 2: warp-specialized fused stream-K GEMM
//   out[8192,512] += S(x)[8192,4096] @ B[512,4096]^T   (out pre-zeroed)
// Warps 0-7: the proven R5 compute loop (ldmatrix double-buffer + mma).
// Warps 8-9 (64 threads): producers. Per chunk they LDG x (prefetched one
// iteration ahead), expand via closed-form basis into the stage-A smem
// region, issue the B cp.async + commit + wait_group. One __syncthreads per
// chunk publishes stage g+2 before its first reader (iter g+1, kk3 prefetch).
// ---------------------------------------------------------------------------
__global__ void __launch_bounds__(NTHREADS, 1) bspline_gemm_kernel(
    const float* __restrict__ x, float* __restrict__ out, int ncta)
{
    extern __shared__ char smem[];
    const uint32_t sb = smem_u32(smem);
    const int tid  = threadIdx.x;
    const int lane = tid & 31;
    const int warp = tid >> 5;

    const int c0 = (int)((long long)blockIdx.x       * TOTAL_UNITS / ncta);
    const int c1 = (int)((long long)(blockIdx.x + 1) * TOTAL_UNITS / ncta);

    if (warp >= 8) {
        // =================== PRODUCER: warps 8-9 (64 threads) ===============
        const int ptid = tid - 256;           // 0..63
        const int row0 = ptid * 2;            // rows row0, row0+1

        // B loader: 1024 x 16B per chunk, 16 per thread
        auto load_chunkB = [&](int g) {
            const int kc    = g & 63;
            const int ntile = (g >> 6) & 3;
            const __half* gB = g_B + (size_t)ntile * BN * KDIM + kc * BK;
            const uint32_t base = sb + (g & 3) * STAGE_BYTES + A_BYTES;
#pragma unroll
            for (int t4 = 0; t4 < 16; t4++) {
                int cid = ptid + t4 * 64;                // 0..1023
                int row = cid >> 3;
                int cc  = cid & 7;
                uint32_t soff = row * 128 + ((cc ^ (row & 7)) << 4);
                const __half* gb = gB + (size_t)row * KDIM + cc * 8;
                asm volatile("cp.async.cg.shared.global [%0], [%1], 16;"
                             :: "r"(base + soff), "l"(gb));
            }
        };
        // x loader for chunk g: 8 x-values per row, rows row0 & row0+1
        auto ldg_x = [&](int g, float4* v) {
            const int mtile = (g >> 6) >> 2;
            const int kc    = g & 63;
            const float* p0 = x + (size_t)(mtile * BM + row0) * IN_SIZE + kc * 8;
            v[0] = *reinterpret_cast<const float4*>(p0);
            v[1] = *reinterpret_cast<const float4*>(p0 + 4);
            v[2] = *reinterpret_cast<const float4*>(p0 + IN_SIZE);
            v[3] = *reinterpret_cast<const float4*>(p0 + IN_SIZE + 4);
        };
        // basis expand + STS one row (8 cells = 8 x 16B, full 128B row)
        auto sts_row = [&](uint32_t sA, int row, float4 u, float4 v) {
            float xs[8] = {u.x, u.y, u.z, u.w, v.x, v.y, v.z, v.w};
#pragma unroll
            for (int c = 0; c < 8; c++) {
                uint4 t = basis8(xs[c]);
                uint32_t a = sA + row * 128 + ((c ^ (row & 7)) << 4);
                asm volatile("st.shared.v4.b32 [%0], {%1,%2,%3,%4};"
                             :: "r"(a), "r"(t.x), "r"(t.y), "r"(t.z), "r"(t.w));
            }
        };
        auto sts_A = [&](int g, const float4* v) {
            const uint32_t sA = sb + (g & 3) * STAGE_BYTES;
            sts_row(sA, row0,     v[0], v[1]);
            sts_row(sA, row0 + 1, v[2], v[3]);
        };

        // ---- prologue -----------------------------------------------------
#pragma unroll
        for (int p = 0; p < STAGES - 1; p++) {
            if (c0 + p < c1) load_chunkB(c0 + p);
            asm volatile("cp.async.commit_group;" ::: "memory");
        }
        float4 xv[4];
        ldg_x(c0, xv);     sts_A(c0, xv);
        if (c0 + 1 < c1) { ldg_x(c0 + 1, xv); sts_A(c0 + 1, xv); }
        if (c0 + 2 < c1)   ldg_x(c0 + 2, xv);        // carry for iter c0
        asm volatile("cp.async.wait_group 1;" ::: "memory");
        __syncthreads();

        for (int g = c0; g < c1; g++) {
            float4 nx[4];
            if (g + 3 < c1) ldg_x(g + 3, nx);        // prefetch next carry
            if (g + STAGES - 1 < c1) load_chunkB(g + STAGES - 1);
            asm volatile("cp.async.commit_group;" ::: "memory");
            if (g + 2 < c1) sts_A(g + 2, xv);        // expand carried x
#pragma unroll
            for (int q = 0; q < 4; q++) xv[q] = nx[q];
            asm volatile("cp.async.wait_group 1;" ::: "memory");
            __syncthreads();
        }
    } else {
        // =================== COMPUTE: warps 0-7 (R5 loop, unchanged) ========
        const int wm = warp & 1;     // 0..1  (64 rows)
        const int wn = warp >> 1;    // 0..3  (32 cols)

        auto load_frags = [&](int g, int kk, uint32_t (*ar)[4], uint32_t (*br)[2]) {
            const uint32_t sA = sb + (g & 3) * STAGE_BYTES;
            const uint32_t sB = sA + A_BYTES;
#pragma unroll
            for (int mt = 0; mt < 4; mt++) {
                int row = wm * 64 + mt * 16 + (lane & 15);
                int kch = kk * 2 + (lane >> 4);
                uint32_t addr = sA + row * 128 + ((kch ^ (row & 7)) << 4);
                asm volatile("ldmatrix.sync.aligned.m8n8.x4.shared.b16 "
                             "{%0,%1,%2,%3}, [%4];"
                             : "=r"(ar[mt][0]), "=r"(ar[mt][1]),
                               "=r"(ar[mt][2]), "=r"(ar[mt][3])
                             : "r"(addr));
            }
#pragma unroll
            for (int nt2 = 0; nt2 < 2; nt2++) {
                int row = wn * 32 + nt2 * 16 + (lane & 7) + ((lane >> 4) << 3);
                int kch = kk * 2 + ((lane >> 3) & 1);
                uint32_t addr = sB + row * 128 + ((kch ^ (row & 7)) << 4);
                asm volatile("ldmatrix.sync.aligned.m8n8.x4.shared.b16 "
                             "{%0,%1,%2,%3}, [%4];"
                             : "=r"(br[nt2 * 2][0]),     "=r"(br[nt2 * 2][1]),
                               "=r"(br[nt2 * 2 + 1][0]), "=r"(br[nt2 * 2 + 1][1])
                             : "r"(addr));
            }
        };

        __syncthreads();               // matches producer prologue barrier

        uint32_t ar[2][4][4], br[2][4][2];
        float acc[4][4][4] = {};

        load_frags(c0, 0, ar[0], br[0]);

        for (int g = c0; g < c1; g++) {
#pragma unroll
            for (int kk = 0; kk < 4; kk++) {
                if (kk < 3)          load_frags(g,     kk + 1, ar[(kk + 1) & 1], br[(kk + 1) & 1]);
                else if (g + 1 < c1) load_frags(g + 1, 0,      ar[0],            br[0]);
                const int b = kk & 1;
#pragma unroll
                for (int mt = 0; mt < 4; mt++)
#pragma unroll
                    for (int nt = 0; nt < 4; nt++)
                        asm volatile(
                            "mma.sync.aligned.m16n8k16.row.col.f32.f16.f16.f32 "
                            "{%0,%1,%2,%3}, {%4,%5,%6,%7}, {%8,%9}, {%0,%1,%2,%3};"
                            : "+f"(acc[mt][nt][0]), "+f"(acc[mt][nt][1]),
                              "+f"(acc[mt][nt][2]), "+f"(acc[mt][nt][3])
                            : "r"(ar[b][mt][0]), "r"(ar[b][mt][1]),
                              "r"(ar[b][mt][2]), "r"(ar[b][mt][3]),
                              "r"(br[b][nt][0]), "r"(br[b][nt][1]));
            }

            // ---- segment flush: tile finished, or end of range ------------
            if (((g & 63) == 63) || (g == c1 - 1)) {
                const int t     = g >> 6;
                const int mtile = t >> 2;
                const int ntile = t & 3;
#pragma unroll
                for (int mt = 0; mt < 4; mt++) {
                    int r0 = mtile * BM + wm * 64 + mt * 16 + (lane >> 2);
#pragma unroll
                    for (int nt = 0; nt < 4; nt++) {
                        int cc = ntile * BN + wn * 32 + nt * 8 + (lane & 3) * 2;
                        float* p0 = out + (size_t)r0 * OUT_SIZE + cc;
                        float* p1 = out + (size_t)(r0 + 8) * OUT_SIZE + cc;
                        atomicAdd(p0,     acc[mt][nt][0]);
                        atomicAdd(p0 + 1, acc[mt][nt][1]);
                        atomicAdd(p1,     acc[mt][nt][2]);
                        atomicAdd(p1 + 1, acc[mt][nt][3]);
                        acc[mt][nt][0] = 0.f; acc[mt][nt][1] = 0.f;
                        acc[mt][nt][2] = 0.f; acc[mt][nt][3] = 0.f;
                    }
                }
            }

            __syncthreads();           // stage g+2 (A and B) now published
        }
    }
}

// ---------------------------------------------------------------------------
// Host: kernel_launch (graph-capturable, allocation-free)
// ---------------------------------------------------------------------------
extern "C" void kernel_launch(void* const* d_in, const int* in_sizes, int n_in,
                              void* d_out, int out_size) {
    const float* x    = (const float*)d_in[0];
    const float* w    = (const float*)d_in[1];
    const float* coef = (const float*)d_in[2];
    float*       out  = (float*)d_out;

    int nsm = 148;
    cudaDeviceGetAttribute(&nsm, cudaDevAttrMultiProcessorCount, 0);

    cudaMemsetAsync(out, 0, (size_t)BATCH * OUT_SIZE * sizeof(float));

    prep_kernel<<<(OUT_SIZE * IN_SIZE) / 256, 256>>>(w, coef);

    cudaFuncSetAttribute(bspline_gemm_kernel,
                         cudaFuncAttributeMaxDynamicSharedMemorySize, SMEM_TOTAL);
    bspline_gemm_kernel<<<nsm, NTHREADS, SMEM_TOTAL>>>(x, out, nsm);
}

// round 9
// speedup vs baseline: 11.9314x; 11.9314x over previous
#include <cuda_runtime.h>
#include <cuda_fp16.h>
#include <cstdint>

// ---------------------------------------------------------------------------
// Problem constants
// ---------------------------------------------------------------------------
#define BATCH    8192
#define IN_SIZE  512
#define OUT_SIZE 512
#define KDIM     (IN_SIZE * 8)        // 4096

// GEMM tiling: CTA 128x64, 4 warps (2M x 2N), warp tile 64x32. 2 CTAs/SM.
#define BM       128
#define BN       64
#define BK       64                    // 64 fp16 = 128 B rows
#define STAGES   4
#define NTILES_N (OUT_SIZE / BN)       // 8
#define NTILES_M (BATCH / BM)          // 64
#define NKC      (KDIM / BK)           // 64
#define TOTAL_UNITS (NTILES_M * NTILES_N * NKC)   // 32768
#define A_BYTES  (BM * 128)            // 16384
#define B_BYTES  (BN * 128)            // 8192
#define STAGE_BYTES (A_BYTES + B_BYTES)          // 24576
#define SMEM_TOTAL  (STAGES * STAGE_BYTES)       // 98304

// prep/basis/zero fused kernel block ranges (256 threads each)
#define PREP_BLOCKS  ((OUT_SIZE * IN_SIZE) / 256)          // 1024
#define BASIS_BLOCKS ((BATCH * IN_SIZE) / 256)             // 16384
#define ZERO_BLOCKS  ((BATCH * OUT_SIZE) / (256 * 4))      // 4096 (uint4 zeros)

// ---------------------------------------------------------------------------
// Scratch (device globals -- no cudaMalloc allowed)
// ---------------------------------------------------------------------------
__device__ __half g_S[(size_t)BATCH * KDIM];      // 64 MB: spline basis, fp16
__device__ __half g_B[(size_t)OUT_SIZE * KDIM];   // 4 MB: coeff*weight, fp16

__device__ __forceinline__ uint32_t smem_u32(const void* p) {
    uint32_t a;
    asm("{ .reg .u64 t; cvta.to.shared.u64 t, %1; cvt.u32.u64 %0, t; }"
        : "=r"(a) : "l"(p));
    return a;
}

// ---------------------------------------------------------------------------
// Kernel 1: fused prep + basis + output zeroing
//   blocks [0, PREP):          g_B[o, i*8+g] = coeff[o,i,g] * w[o,i]
//   blocks [PREP, PREP+BASIS): g_S[b, i*8+g] = basis_g(clamp(x[b,i]))
//   blocks [.., +ZERO):        out[...] = 0   (gemm accumulates via atomics)
// ---------------------------------------------------------------------------
__global__ void prep_basis_zero_kernel(const float* __restrict__ x,
                                       const float* __restrict__ w,
                                       const float* __restrict__ coef,
                                       float* __restrict__ out) {
    if (blockIdx.x < PREP_BLOCKS) {
        int idx = blockIdx.x * blockDim.x + threadIdx.x;   // (o, i)
        float wv = w[idx];
        const float4* c4 = reinterpret_cast<const float4*>(coef) + (size_t)idx * 2;
        float4 a = c4[0], b = c4[1];
        union { uint4 u; __half2 h[4]; } v;
        v.h[0] = __floats2half2_rn(a.x * wv, a.y * wv);
        v.h[1] = __floats2half2_rn(a.z * wv, a.w * wv);
        v.h[2] = __floats2half2_rn(b.x * wv, b.y * wv);
        v.h[3] = __floats2half2_rn(b.z * wv, b.w * wv);
        reinterpret_cast<uint4*>(g_B)[idx] = v.u;
    } else if (blockIdx.x < PREP_BLOCKS + BASIS_BLOCKS) {
        int idx = (blockIdx.x - PREP_BLOCKS) * blockDim.x + threadIdx.x;  // (b, i)
        float xv = x[idx];
        xv = fminf(1.0f, fmaxf(-1.0f, xv));
        float u = (xv + 1.0f) * 3.5f;          // / h, h = 2/7
        int i = min(7, (int)u);
        float t = u - (float)i;
        const float k6 = 1.0f / 6.0f;
        float t2 = t * t, t3 = t2 * t, omt = 1.0f - t;
        float v0 = t3 * k6;
        float v1 = (1.0f + 3.0f * (t + t2 - t3)) * k6;
        float v2 = (4.0f - 6.0f * t2 + 3.0f * t3) * k6;
        float v3 = omt * omt * omt * k6;
        float o[8];
#pragma unroll
        for (int j = 0; j < 8; j++) {
            int d = i - j;
            o[j] = (d == 0) ? v0 : (d == 1) ? v1 : (d == 2) ? v2
                 : (d == 3) ? v3 : 0.0f;
        }
        union { uint4 uu; __half2 hh[4]; } v;
        v.hh[0] = __floats2half2_rn(o[0], o[1]);
        v.hh[1] = __floats2half2_rn(o[2], o[3]);
        v.hh[2] = __floats2half2_rn(o[4], o[5]);
        v.hh[3] = __floats2half2_rn(o[6], o[7]);
        reinterpret_cast<uint4*>(g_S)[idx] = v.uu;
    } else {
        int idx = (blockIdx.x - PREP_BLOCKS - BASIS_BLOCKS) * blockDim.x + threadIdx.x;
        reinterpret_cast<uint4*>(out)[idx] = make_uint4(0, 0, 0, 0);
    }
}

// ---------------------------------------------------------------------------
// Kernel 2: stream-K persistent GEMM, 2 CTAs/SM for barrier-stall overlap
//   out[8192,512] += S[8192,4096] @ B[512,4096]^T   (out pre-zeroed)
// CTA tile 128x64, 4 warps (2M x 2N), warp tile 64x32 -- identical per-warp
// inner loop, fragment double-buffering, and cross-chunk prefetch as the
// proven R5 kernel. Two CTAs per SM interleave on the SMSPs so one CTA's
// barrier/wait_group stalls are covered by the other's mma issue.
// ---------------------------------------------------------------------------
__global__ void __launch_bounds__(128, 2) bspline_gemm_kernel(float* __restrict__ out,
                                                              int ncta)
{
    extern __shared__ char smem[];
    const uint32_t sb = smem_u32(smem);
    const int tid  = threadIdx.x;
    const int lane = tid & 31;
    const int warp = tid >> 5;
    const int wm   = warp & 1;    // 0..1  (64 rows)
    const int wn   = warp >> 1;   // 0..1  (32 cols)

    const int c0 = (int)((long long)blockIdx.x       * TOTAL_UNITS / ncta);
    const int c1 = (int)((long long)(blockIdx.x + 1) * TOTAL_UNITS / ncta);

    // unit g: tile = g>>6 (= mtile*8 + ntile), kchunk = g&63
    auto load_chunk = [&](int g) {
        const int t     = g >> 6;
        const int kc    = g & 63;
        const int mtile = t >> 3;
        const int ntile = t & 7;
        const __half* gA = g_S + (size_t)mtile * BM * KDIM + kc * BK;
        const __half* gB = g_B + (size_t)ntile * BN * KDIM + kc * BK;
        const uint32_t base = sb + (g & 3) * STAGE_BYTES;
#pragma unroll
        for (int t8 = 0; t8 < 8; t8++) {          // A: 1024 x 16B
            int cid = tid + t8 * 128;
            int row = cid >> 3;
            int cc  = cid & 7;
            uint32_t soff = row * 128 + ((cc ^ (row & 7)) << 4);
            const __half* ga = gA + (size_t)row * KDIM + cc * 8;
            asm volatile("cp.async.cg.shared.global [%0], [%1], 16;"
                         :: "r"(base + soff), "l"(ga));
        }
#pragma unroll
        for (int t4 = 0; t4 < 4; t4++) {          // B: 512 x 16B
            int cid = tid + t4 * 128;
            int row = cid >> 3;
            int cc  = cid & 7;
            uint32_t soff = row * 128 + ((cc ^ (row & 7)) << 4);
            const __half* gb = gB + (size_t)row * KDIM + cc * 8;
            asm volatile("cp.async.cg.shared.global [%0], [%1], 16;"
                         :: "r"(base + A_BYTES + soff), "l"(gb));
        }
    };

    auto load_frags = [&](int g, int kk, uint32_t (*ar)[4], uint32_t (*br)[2]) {
        const uint32_t sA = sb + (g & 3) * STAGE_BYTES;
        const uint32_t sB = sA + A_BYTES;
#pragma unroll
        for (int mt = 0; mt < 4; mt++) {
            int row = wm * 64 + mt * 16 + (lane & 15);
            int kch = kk * 2 + (lane >> 4);
            uint32_t addr = sA + row * 128 + ((kch ^ (row & 7)) << 4);
            asm volatile("ldmatrix.sync.aligned.m8n8.x4.shared.b16 "
                         "{%0,%1,%2,%3}, [%4];"
                         : "=r"(ar[mt][0]), "=r"(ar[mt][1]),
                           "=r"(ar[mt][2]), "=r"(ar[mt][3])
                         : "r"(addr));
        }
#pragma unroll
        for (int nt2 = 0; nt2 < 2; nt2++) {
            int row = wn * 32 + nt2 * 16 + (lane & 7) + ((lane >> 4) << 3);
            int kch = kk * 2 + ((lane >> 3) & 1);
            uint32_t addr = sB + row * 128 + ((kch ^ (row & 7)) << 4);
            asm volatile("ldmatrix.sync.aligned.m8n8.x4.shared.b16 "
                         "{%0,%1,%2,%3}, [%4];"
                         : "=r"(br[nt2 * 2][0]),     "=r"(br[nt2 * 2][1]),
                           "=r"(br[nt2 * 2 + 1][0]), "=r"(br[nt2 * 2 + 1][1])
                         : "r"(addr));
        }
    };

    // ---- prologue: prefetch 3 chunks, stages c0 & c0+1 visible ------------
#pragma unroll
    for (int p = 0; p < STAGES - 1; p++) {
        if (c0 + p < c1) load_chunk(c0 + p);
        asm volatile("cp.async.commit_group;" ::: "memory");
    }
    asm volatile("cp.async.wait_group 1;" ::: "memory");
    __syncthreads();

    uint32_t ar[2][4][4], br[2][4][2];
    float acc[4][4][4] = {};

    load_frags(c0, 0, ar[0], br[0]);

    for (int g = c0; g < c1; g++) {
        if (g + STAGES - 1 < c1) load_chunk(g + STAGES - 1);
        asm volatile("cp.async.commit_group;" ::: "memory");

#pragma unroll
        for (int kk = 0; kk < 4; kk++) {
            if (kk < 3)          load_frags(g,     kk + 1, ar[(kk + 1) & 1], br[(kk + 1) & 1]);
            else if (g + 1 < c1) load_frags(g + 1, 0,      ar[0],            br[0]);
            const int b = kk & 1;
#pragma unroll
            for (int mt = 0; mt < 4; mt++)
#pragma unroll
                for (int nt = 0; nt < 4; nt++)
                    asm volatile(
                        "mma.sync.aligned.m16n8k16.row.col.f32.f16.f16.f32 "
                        "{%0,%1,%2,%3}, {%4,%5,%6,%7}, {%8,%9}, {%0,%1,%2,%3};"
                        : "+f"(acc[mt][nt][0]), "+f"(acc[mt][nt][1]),
                          "+f"(acc[mt][nt][2]), "+f"(acc[mt][nt][3])
                        : "r"(ar[b][mt][0]), "r"(ar[b][mt][1]),
                          "r"(ar[b][mt][2]), "r"(ar[b][mt][3]),
                          "r"(br[b][nt][0]), "r"(br[b][nt][1]));
        }

        // ---- segment flush: tile finished, or end of this CTA's range -----
        if (((g & 63) == 63) || (g == c1 - 1)) {
            const int t     = g >> 6;
            const int mtile = t >> 3;
            const int ntile = t & 7;
#pragma unroll
            for (int mt = 0; mt < 4; mt++) {
                int r0 = mtile * BM + wm * 64 + mt * 16 + (lane >> 2);
#pragma unroll
                for (int nt = 0; nt < 4; nt++) {
                    int cc = ntile * BN + wn * 32 + nt * 8 + (lane & 3) * 2;
                    float* p0 = out + (size_t)r0 * OUT_SIZE + cc;
                    float* p1 = out + (size_t)(r0 + 8) * OUT_SIZE + cc;
                    atomicAdd(p0,     acc[mt][nt][0]);
                    atomicAdd(p0 + 1, acc[mt][nt][1]);
                    atomicAdd(p1,     acc[mt][nt][2]);
                    atomicAdd(p1 + 1, acc[mt][nt][3]);
                    acc[mt][nt][0] = 0.f; acc[mt][nt][1] = 0.f;
                    acc[mt][nt][2] = 0.f; acc[mt][nt][3] = 0.f;
                }
            }
        }

        // stage g+2 visible next iteration; guards stage reuse.
        asm volatile("cp.async.wait_group 1;" ::: "memory");
        __syncthreads();
    }
}

// ---------------------------------------------------------------------------
// Host: kernel_launch (graph-capturable, allocation-free)
// ---------------------------------------------------------------------------
extern "C" void kernel_launch(void* const* d_in, const int* in_sizes, int n_in,
                              void* d_out, int out_size) {
    const float* x    = (const float*)d_in[0];
    const float* w    = (const float*)d_in[1];
    const float* coef = (const float*)d_in[2];
    float*       out  = (float*)d_out;

    int nsm = 148;
    cudaDeviceGetAttribute(&nsm, cudaDevAttrMultiProcessorCount, 0);
    const int ncta = 2 * nsm;          // 2 persistent CTAs per SM

    prep_basis_zero_kernel<<<PREP_BLOCKS + BASIS_BLOCKS + ZERO_BLOCKS, 256>>>(
        x, w, coef, out);

    cudaFuncSetAttribute(bspline_gemm_kernel,
                         cudaFuncAttributeMaxDynamicSharedMemorySize, SMEM_TOTAL);
    bspline_gemm_kernel<<<ncta, 128, SMEM_TOTAL>>>(out, ncta);
}